// round 15
// baseline (speedup 1.0000x reference)
#include <cuda_runtime.h>
#include <stdint.h>

#define N_NODES 50000
#define N_EDGES 600000
#define IN_DIM 128
#define HID 256
#define N_CLASSES 16

#define SCAN_BLOCK 256
#define N_SBLOCKS ((N_NODES + SCAN_BLOCK - 1) / SCAN_BLOCK)   // 196

// ---------------- device scratch (no allocation allowed) ----------------
__device__ int   g_cnt[N_NODES];
__device__ int   g_blockoff[N_SBLOCKS];
__device__ int   g_rowptr[N_NODES + 1];
__device__ int   g_cursor[N_NODES];
__device__ int   g_col[N_EDGES];
__device__ float g_agg[(size_t)N_NODES * HID];
__device__ float g_h1[(size_t)N_NODES * HID];
__device__ float g_h2[(size_t)N_NODES * HID];
__device__ float g_w1t[2 * IN_DIM * HID];         // [w1_l ; w1_r] tf32
__device__ float g_w2t[2 * HID * HID];            // [w2_l ; w2_r] tf32

// ---------------- helpers ----------------
__device__ __forceinline__ float to_tf32(float x) {
    uint32_t u;
    asm("cvt.rna.tf32.f32 %0, %1;" : "=r"(u) : "f"(x));
    return __uint_as_float(u);
}

__device__ __forceinline__ void mma_tf32(float* d, const uint32_t* a, uint32_t b0, uint32_t b1) {
    asm volatile(
        "mma.sync.aligned.m16n8k8.row.col.f32.tf32.tf32.f32 "
        "{%0,%1,%2,%3}, {%4,%5,%6,%7}, {%8,%9}, {%0,%1,%2,%3};"
        : "+f"(d[0]), "+f"(d[1]), "+f"(d[2]), "+f"(d[3])
        : "r"(a[0]), "r"(a[1]), "r"(a[2]), "r"(a[3]), "r"(b0), "r"(b1));
}

__device__ __forceinline__ void f4add(float4& a, const float4 b) {
    a.x += b.x; a.y += b.y; a.z += b.z; a.w += b.w;
}

// ---------------- prep: zero cnt + weight tf32 cvts ----------------
__global__ void prep_k(const float* __restrict__ w1_l, const float* __restrict__ w1_r,
                       const float* __restrict__ w2_l, const float* __restrict__ w2_r) {
    int i = blockIdx.x * blockDim.x + threadIdx.x;
    if (i < N_NODES) g_cnt[i] = 0;
    const int H1 = IN_DIM * HID;
    if (i < 2 * H1)
        g_w1t[i] = to_tf32(i < H1 ? w1_l[i] : w1_r[i - H1]);
    const int H2 = HID * HID;
    if (i < 2 * H2)
        g_w2t[i] = to_tf32(i < H2 ? w2_l[i] : w2_r[i - H2]);
}

// ---------------- CSR build ----------------
__global__ void hist_kernel(const int* __restrict__ ei) {
    int e = blockIdx.x * blockDim.x + threadIdx.x;
    if (e >= N_EDGES) return;
    int d = min(max(ei[N_EDGES + e], 0), N_NODES - 1);
    atomicAdd(&g_cnt[d], 1);
}
__global__ void block_reduce_k() {
    __shared__ int sm[SCAN_BLOCK];
    int i = blockIdx.x * SCAN_BLOCK + threadIdx.x;
    sm[threadIdx.x] = (i < N_NODES) ? g_cnt[i] : 0;
    __syncthreads();
#pragma unroll
    for (int o = SCAN_BLOCK / 2; o > 0; o >>= 1) {
        if (threadIdx.x < o) sm[threadIdx.x] += sm[threadIdx.x + o];
        __syncthreads();
    }
    if (threadIdx.x == 0) g_blockoff[blockIdx.x] = sm[0];
}
__global__ void scan_blocksums_k() {
    __shared__ int sm[256];
    int t = threadIdx.x;
    int v = (t < N_SBLOCKS) ? g_blockoff[t] : 0;
    sm[t] = v;
    __syncthreads();
#pragma unroll
    for (int o = 1; o < 256; o <<= 1) {
        int u = (t >= o) ? sm[t - o] : 0;
        __syncthreads();
        sm[t] += u;
        __syncthreads();
    }
    if (t < N_SBLOCKS) g_blockoff[t] = sm[t] - v;
}
__global__ void block_scan_k() {
    __shared__ int sm[SCAN_BLOCK];
    int i = blockIdx.x * SCAN_BLOCK + threadIdx.x;
    int v = (i < N_NODES) ? g_cnt[i] : 0;
    sm[threadIdx.x] = v;
    __syncthreads();
#pragma unroll
    for (int o = 1; o < SCAN_BLOCK; o <<= 1) {
        int u = (threadIdx.x >= o) ? sm[threadIdx.x - o] : 0;
        __syncthreads();
        sm[threadIdx.x] += u;
        __syncthreads();
    }
    if (i < N_NODES) {
        int excl = sm[threadIdx.x] - v + g_blockoff[blockIdx.x];
        g_rowptr[i] = excl;
        g_cursor[i] = excl;
    }
    if (i == 0) g_rowptr[N_NODES] = N_EDGES;
}
__global__ void fill_kernel(const int* __restrict__ ei) {
    int e = blockIdx.x * blockDim.x + threadIdx.x;
    if (e >= N_EDGES) return;
    int s = min(max(ei[e], 0), N_NODES - 1);
    int d = min(max(ei[N_EDGES + e], 0), N_NODES - 1);
    int pos = atomicAdd(&g_cursor[d], 1);
    g_col[pos] = s;
}

// ---------------- gather mean (CSR), fp32 ----------------
__global__ void gather_mean_128(const float* __restrict__ feat) {
    int w = (blockIdx.x * blockDim.x + threadIdx.x) >> 5;
    int lane = threadIdx.x & 31;
    if (w >= N_NODES) return;
    int beg = g_rowptr[w], end = g_rowptr[w + 1];
    float4 acc = make_float4(0.f, 0.f, 0.f, 0.f);
    int j = beg;
    for (; j + 4 <= end; j += 4) {
        int s0 = __ldg(&g_col[j + 0]);
        int s1 = __ldg(&g_col[j + 1]);
        int s2 = __ldg(&g_col[j + 2]);
        int s3 = __ldg(&g_col[j + 3]);
        float4 v0 = __ldg(reinterpret_cast<const float4*>(feat + (size_t)s0 * IN_DIM) + lane);
        float4 v1 = __ldg(reinterpret_cast<const float4*>(feat + (size_t)s1 * IN_DIM) + lane);
        float4 v2 = __ldg(reinterpret_cast<const float4*>(feat + (size_t)s2 * IN_DIM) + lane);
        float4 v3 = __ldg(reinterpret_cast<const float4*>(feat + (size_t)s3 * IN_DIM) + lane);
        f4add(acc, v0); f4add(acc, v1); f4add(acc, v2); f4add(acc, v3);
    }
    for (; j < end; j++) {
        int s = __ldg(&g_col[j]);
        float4 v = __ldg(reinterpret_cast<const float4*>(feat + (size_t)s * IN_DIM) + lane);
        f4add(acc, v);
    }
    float inv = 1.0f / (float)max(end - beg, 1);
    float4 o;
    o.x = to_tf32(acc.x * inv); o.y = to_tf32(acc.y * inv);
    o.z = to_tf32(acc.z * inv); o.w = to_tf32(acc.w * inv);
    reinterpret_cast<float4*>(g_agg + (size_t)w * IN_DIM)[lane] = o;
}

// two warps per node: warp-half h handles float4s [h*32 .. h*32+31] of the 256-wide row
__global__ void gather_mean_256() {
    int gw = (blockIdx.x * blockDim.x + threadIdx.x) >> 5;
    int node = gw >> 1;
    int half = gw & 1;
    int lane = threadIdx.x & 31;
    if (node >= N_NODES) return;
    int beg = g_rowptr[node], end = g_rowptr[node + 1];
    int fo = half * 32 + lane;
    const float4* h1v = reinterpret_cast<const float4*>(g_h1);
    float4 acc = make_float4(0.f, 0.f, 0.f, 0.f);
    int j = beg;
    for (; j + 4 <= end; j += 4) {
        int s0 = __ldg(&g_col[j + 0]);
        int s1 = __ldg(&g_col[j + 1]);
        int s2 = __ldg(&g_col[j + 2]);
        int s3 = __ldg(&g_col[j + 3]);
        float4 v0 = __ldg(h1v + (size_t)s0 * (HID / 4) + fo);
        float4 v1 = __ldg(h1v + (size_t)s1 * (HID / 4) + fo);
        float4 v2 = __ldg(h1v + (size_t)s2 * (HID / 4) + fo);
        float4 v3 = __ldg(h1v + (size_t)s3 * (HID / 4) + fo);
        f4add(acc, v0); f4add(acc, v1); f4add(acc, v2); f4add(acc, v3);
    }
    for (; j < end; j++) {
        int s = __ldg(&g_col[j]);
        f4add(acc, __ldg(h1v + (size_t)s * (HID / 4) + fo));
    }
    float inv = 1.0f / (float)max(end - beg, 1);
    float4 o;
    o.x = to_tf32(acc.x * inv); o.y = to_tf32(acc.y * inv);
    o.z = to_tf32(acc.z * inv); o.w = to_tf32(acc.w * inv);
    reinterpret_cast<float4*>(g_agg)[(size_t)node * (HID / 4) + fo] = o;
}

// ---------------- tf32 tensor-core SAGE GEMM, BM=128 BN=256 BK=32, 512 thr ----------------
#define AS_STRIDE 36
#define BS_STRIDE 264
#define AS_BUF (128 * AS_STRIDE)
#define BS_BUF (32 * BS_STRIDE)

template <int KHALF, bool CVT_A, bool CVT_OUT>
__global__ void __launch_bounds__(512, 1)
sage_tf32(const float* __restrict__ A0, const float* __restrict__ A1,
          const float* __restrict__ W, const float* __restrict__ bias,
          float* __restrict__ C) {
    extern __shared__ float smem[];
    float* As = smem;
    float* Bs = smem + 2 * AS_BUF;

    const int tid = threadIdx.x;
    const int lane = tid & 31;
    const int wid = tid >> 5;
    const int wm = wid & 3;
    const int wn = wid >> 2;
    const int rowBase = blockIdx.x * 128;
    const int NT = (2 * KHALF) / 32;

    float acc[2][8][4];
#pragma unroll
    for (int i = 0; i < 2; i++)
#pragma unroll
        for (int j = 0; j < 8; j++)
#pragma unroll
            for (int k = 0; k < 4; k++) acc[i][j][k] = 0.0f;

    auto issue = [&](int buf, int k0) {
        float* Asb = As + buf * AS_BUF;
        float* Bsb = Bs + buf * BS_BUF;
        const float* Abase = (k0 < KHALF) ? A0 : A1;
        int kb = (k0 < KHALF) ? k0 : (k0 - KHALF);
#pragma unroll
        for (int i = 0; i < 2; i++) {
            int idx = tid + 512 * i;
            int r = idx >> 3, kc = idx & 7;
            int row = rowBase + r;
            const float* src = Abase + (size_t)row * KHALF + kb + kc * 4;
            uint32_t dst = (uint32_t)__cvta_generic_to_shared(Asb + r * AS_STRIDE + kc * 4);
            int sz = (row < N_NODES) ? 16 : 0;
            asm volatile("cp.async.ca.shared.global [%0], [%1], 16, %2;"
                         :: "r"(dst), "l"(src), "r"(sz));
        }
#pragma unroll
        for (int i = 0; i < 4; i++) {
            int idx = tid + 512 * i;
            int k = idx >> 6, c4 = idx & 63;
            const float* src = W + (size_t)(k0 + k) * HID + c4 * 4;
            uint32_t dst = (uint32_t)__cvta_generic_to_shared(Bsb + k * BS_STRIDE + c4 * 4);
            asm volatile("cp.async.ca.shared.global [%0], [%1], 16;"
                         :: "r"(dst), "l"(src));
        }
        asm volatile("cp.async.commit_group;");
    };

    issue(0, 0);
    for (int t = 0; t < NT; t++) {
        if (t + 1 < NT) {
            issue((t + 1) & 1, (t + 1) * 32);
            asm volatile("cp.async.wait_group 1;");
        } else {
            asm volatile("cp.async.wait_group 0;");
        }
        __syncthreads();
        const float* Asb = As + (t & 1) * AS_BUF;
        const float* Bsb = Bs + (t & 1) * BS_BUF;
#pragma unroll
        for (int k8 = 0; k8 < 4; k8++) {
            int kb = k8 * 8;
            uint32_t a[2][4];
#pragma unroll
            for (int mt = 0; mt < 2; mt++) {
                int m = wm * 32 + mt * 16 + (lane >> 2);
                int k = kb + (lane & 3);
                float a0 = Asb[m * AS_STRIDE + k];
                float a1 = Asb[(m + 8) * AS_STRIDE + k];
                float a2 = Asb[m * AS_STRIDE + k + 4];
                float a3 = Asb[(m + 8) * AS_STRIDE + k + 4];
                if (CVT_A) { a0 = to_tf32(a0); a1 = to_tf32(a1); a2 = to_tf32(a2); a3 = to_tf32(a3); }
                a[mt][0] = __float_as_uint(a0);
                a[mt][1] = __float_as_uint(a1);
                a[mt][2] = __float_as_uint(a2);
                a[mt][3] = __float_as_uint(a3);
            }
#pragma unroll
            for (int nt = 0; nt < 8; nt++) {
                int n = wn * 64 + nt * 8 + (lane >> 2);
                int k = kb + (lane & 3);
                uint32_t b0 = __float_as_uint(Bsb[k * BS_STRIDE + n]);
                uint32_t b1 = __float_as_uint(Bsb[(k + 4) * BS_STRIDE + n]);
                mma_tf32(acc[0][nt], a[0], b0, b1);
                mma_tf32(acc[1][nt], a[1], b0, b1);
            }
        }
        __syncthreads();
    }

#pragma unroll
    for (int mt = 0; mt < 2; mt++) {
        int r0 = rowBase + wm * 32 + mt * 16 + (lane >> 2);
#pragma unroll
        for (int nt = 0; nt < 8; nt++) {
            int c = wn * 64 + nt * 8 + (lane & 3) * 2;
            float bv0 = __ldg(bias + c);
            float bv1 = __ldg(bias + c + 1);
            float v0 = fmaxf(acc[mt][nt][0] + bv0, 0.0f);
            float v1 = fmaxf(acc[mt][nt][1] + bv1, 0.0f);
            float v2 = fmaxf(acc[mt][nt][2] + bv0, 0.0f);
            float v3 = fmaxf(acc[mt][nt][3] + bv1, 0.0f);
            if (CVT_OUT) {
                v0 = to_tf32(v0); v1 = to_tf32(v1);
                v2 = to_tf32(v2); v3 = to_tf32(v3);
            }
            if (r0 < N_NODES)
                *reinterpret_cast<float2*>(C + (size_t)r0 * HID + c) = make_float2(v0, v1);
            if (r0 + 8 < N_NODES)
                *reinterpret_cast<float2*>(C + (size_t)(r0 + 8) * HID + c) = make_float2(v2, v3);
        }
    }
}

// ---------------- classifier ----------------
__global__ void classifier_k(const float* __restrict__ wc,
                             const float* __restrict__ bc,
                             float* __restrict__ out) {
    __shared__ float w[HID * N_CLASSES];
    __shared__ float hrow[8][HID];
    for (int i = threadIdx.x; i < HID * N_CLASSES; i += blockDim.x)
        w[i] = wc[i];
    __syncthreads();

    int warp = threadIdx.x >> 5;
    int lane = threadIdx.x & 31;
    int row = blockIdx.x * 8 + warp;
    if (row >= N_NODES) return;

    const float* h = g_h2 + (size_t)row * HID;
    for (int k = lane; k < HID; k += 32) hrow[warp][k] = h[k];
    __syncwarp();

    int c = lane & 15;
    int p = lane >> 4;
    float acc = 0.0f;
    int kbeg = p * (HID / 2);
#pragma unroll 8
    for (int k = kbeg; k < kbeg + HID / 2; k++)
        acc += hrow[warp][k] * w[k * N_CLASSES + c];
    acc += __shfl_xor_sync(0xffffffffu, acc, 16);
    if (lane < 16) out[(size_t)row * N_CLASSES + lane] = acc + bc[lane];
}

// ---------------- launch ----------------
extern "C" void kernel_launch(void* const* d_in, const int* in_sizes, int n_in,
                              void* d_out, int out_size) {
    const float* x    = (const float*)d_in[0];
    const int*   ei   = (const int*)d_in[1];
    const float* w1_l = (const float*)d_in[2];
    const float* b1_l = (const float*)d_in[3];
    const float* w1_r = (const float*)d_in[4];
    const float* w2_l = (const float*)d_in[5];
    const float* b2_l = (const float*)d_in[6];
    const float* w2_r = (const float*)d_in[7];
    const float* wc   = (const float*)d_in[8];
    const float* bc   = (const float*)d_in[9];
    float* out = (float*)d_out;

    // resolve REAL device addresses (GB300 ATS pitfall: never pass symbols as args)
    void *p_agg, *p_h1, *p_h2, *p_w1t, *p_w2t;
    cudaGetSymbolAddress(&p_agg, g_agg);
    cudaGetSymbolAddress(&p_h1,  g_h1);
    cudaGetSymbolAddress(&p_h2,  g_h2);
    cudaGetSymbolAddress(&p_w1t, g_w1t);
    cudaGetSymbolAddress(&p_w2t, g_w2t);

    const int SMEM = (2 * AS_BUF + 2 * BS_BUF) * 4;   // 104448 B
    cudaFuncSetAttribute(sage_tf32<IN_DIM, true, true>,
                         cudaFuncAttributeMaxDynamicSharedMemorySize, SMEM);
    cudaFuncSetAttribute(sage_tf32<HID, false, false>,
                         cudaFuncAttributeMaxDynamicSharedMemorySize, SMEM);

    // 1: prep (zero cnt + weight cvts)
    prep_k<<<(2 * HID * HID + 255) / 256, 256>>>(w1_l, w1_r, w2_l, w2_r);
    // 2: histogram
    hist_kernel<<<(N_EDGES + 255) / 256, 256>>>(ei);
    // 3: block reduce
    block_reduce_k<<<N_SBLOCKS, SCAN_BLOCK>>>();

    // 4: DIAGNOSTIC duplicate of layer-2 GEMM — ncu profiles my 4th launch.
    //    Reads stale (zero-init / previous-replay) g_agg & g_h1, writes g_h2
    //    which the real layer-2 GEMM below fully overwrites. Output unchanged.
    {
        dim3 grid((N_NODES + 127) / 128, 1);
        sage_tf32<HID, false, false><<<grid, 512, SMEM>>>(
            (const float*)p_agg, (const float*)p_h1, (const float*)p_w2t, b2_l, (float*)p_h2);
    }

    // 5-7: rest of CSR build
    scan_blocksums_k<<<1, 256>>>();
    block_scan_k<<<N_SBLOCKS, SCAN_BLOCK>>>();
    fill_kernel<<<(N_EDGES + 255) / 256, 256>>>(ei);

    // ---- layer 1 ----
    gather_mean_128<<<(N_NODES * 32 + 255) / 256, 256>>>(x);
    {
        dim3 grid((N_NODES + 127) / 128, 1);
        sage_tf32<IN_DIM, true, true><<<grid, 512, SMEM>>>(
            (const float*)p_agg, x, (const float*)p_w1t, b1_l, (float*)p_h1);
    }

    // ---- layer 2 ----
    gather_mean_256<<<(N_NODES * 2 * 32 + 255) / 256, 256>>>();
    {
        dim3 grid((N_NODES + 127) / 128, 1);
        sage_tf32<HID, false, false><<<grid, 512, SMEM>>>(
            (const float*)p_agg, (const float*)p_h1, (const float*)p_w2t, b2_l, (float*)p_h2);
    }

    // ---- classifier ----
    classifier_k<<<(N_NODES + 7) / 8, 256>>>(wc, bc, out);
}

// round 17
// speedup vs baseline: 1.0763x; 1.0763x over previous
#include <cuda_runtime.h>
#include <stdint.h>

#define N_NODES 50000
#define N_EDGES 600000
#define IN_DIM 128
#define HID 256
#define N_CLASSES 16

#define SCAN_BLOCK 256
#define N_SBLOCKS ((N_NODES + SCAN_BLOCK - 1) / SCAN_BLOCK)   // 196

// ---------------- device scratch (no allocation allowed) ----------------
__device__ int   g_cnt[N_NODES];
__device__ int   g_blockoff[N_SBLOCKS];
__device__ int   g_rowptr[N_NODES + 1];
__device__ int   g_cursor[N_NODES];
__device__ int   g_col[N_EDGES];
__device__ float g_agg[(size_t)N_NODES * HID];
__device__ float g_h1[(size_t)N_NODES * HID];
__device__ float g_h2[(size_t)N_NODES * HID];
__device__ float g_w1t[2 * IN_DIM * HID];         // [w1_l ; w1_r] tf32
__device__ float g_w2t[2 * HID * HID];            // [w2_l ; w2_r] tf32

// ---------------- helpers ----------------
__device__ __forceinline__ float to_tf32(float x) {
    uint32_t u;
    asm("cvt.rna.tf32.f32 %0, %1;" : "=r"(u) : "f"(x));
    return __uint_as_float(u);
}
__device__ __forceinline__ void mma_tf32(float* d, const uint32_t* a, uint32_t b0, uint32_t b1) {
    asm volatile(
        "mma.sync.aligned.m16n8k8.row.col.f32.tf32.tf32.f32 "
        "{%0,%1,%2,%3}, {%4,%5,%6,%7}, {%8,%9}, {%0,%1,%2,%3};"
        : "+f"(d[0]), "+f"(d[1]), "+f"(d[2]), "+f"(d[3])
        : "r"(a[0]), "r"(a[1]), "r"(a[2]), "r"(a[3]), "r"(b0), "r"(b1));
}
__device__ __forceinline__ void f4add(float4& a, const float4 b) {
    a.x += b.x; a.y += b.y; a.z += b.z; a.w += b.w;
}

// ---------------- prep: zero cnt + weight tf32 cvts ----------------
__global__ void prep_k(const float* __restrict__ w1_l, const float* __restrict__ w1_r,
                       const float* __restrict__ w2_l, const float* __restrict__ w2_r) {
    int i = blockIdx.x * blockDim.x + threadIdx.x;
    if (i < N_NODES) g_cnt[i] = 0;
    const int H1 = IN_DIM * HID;
    if (i < 2 * H1)
        g_w1t[i] = to_tf32(i < H1 ? w1_l[i] : w1_r[i - H1]);
    const int H2 = HID * HID;
    if (i < 2 * H2)
        g_w2t[i] = to_tf32(i < H2 ? w2_l[i] : w2_r[i - H2]);
}

// ---------------- CSR build ----------------
__global__ void hist_kernel(const int* __restrict__ ei) {
    int e = blockIdx.x * blockDim.x + threadIdx.x;
    if (e >= N_EDGES) return;
    int d = min(max(ei[N_EDGES + e], 0), N_NODES - 1);
    atomicAdd(&g_cnt[d], 1);
}
__global__ void block_reduce_k() {
    __shared__ int sm[SCAN_BLOCK];
    int i = blockIdx.x * SCAN_BLOCK + threadIdx.x;
    sm[threadIdx.x] = (i < N_NODES) ? g_cnt[i] : 0;
    __syncthreads();
#pragma unroll
    for (int o = SCAN_BLOCK / 2; o > 0; o >>= 1) {
        if (threadIdx.x < o) sm[threadIdx.x] += sm[threadIdx.x + o];
        __syncthreads();
    }
    if (threadIdx.x == 0) g_blockoff[blockIdx.x] = sm[0];
}
__global__ void scan_blocksums_k() {
    __shared__ int sm[256];
    int t = threadIdx.x;
    int v = (t < N_SBLOCKS) ? g_blockoff[t] : 0;
    sm[t] = v;
    __syncthreads();
#pragma unroll
    for (int o = 1; o < 256; o <<= 1) {
        int u = (t >= o) ? sm[t - o] : 0;
        __syncthreads();
        sm[t] += u;
        __syncthreads();
    }
    if (t < N_SBLOCKS) g_blockoff[t] = sm[t] - v;
}
__global__ void block_scan_k() {
    __shared__ int sm[SCAN_BLOCK];
    int i = blockIdx.x * SCAN_BLOCK + threadIdx.x;
    int v = (i < N_NODES) ? g_cnt[i] : 0;
    sm[threadIdx.x] = v;
    __syncthreads();
#pragma unroll
    for (int o = 1; o < SCAN_BLOCK; o <<= 1) {
        int u = (threadIdx.x >= o) ? sm[threadIdx.x - o] : 0;
        __syncthreads();
        sm[threadIdx.x] += u;
        __syncthreads();
    }
    if (i < N_NODES) {
        int excl = sm[threadIdx.x] - v + g_blockoff[blockIdx.x];
        g_rowptr[i] = excl;
        g_cursor[i] = excl;
    }
    if (i == 0) g_rowptr[N_NODES] = N_EDGES;
}
__global__ void fill_kernel(const int* __restrict__ ei) {
    int e = blockIdx.x * blockDim.x + threadIdx.x;
    if (e >= N_EDGES) return;
    int s = min(max(ei[e], 0), N_NODES - 1);
    int d = min(max(ei[N_EDGES + e], 0), N_NODES - 1);
    int pos = atomicAdd(&g_cursor[d], 1);
    g_col[pos] = s;
}

// ---------------- gather mean (CSR), fp32 ----------------
__global__ void gather_mean_128(const float* __restrict__ feat) {
    int w = (blockIdx.x * blockDim.x + threadIdx.x) >> 5;
    int lane = threadIdx.x & 31;
    if (w >= N_NODES) return;
    int beg = g_rowptr[w], end = g_rowptr[w + 1];
    float4 acc = make_float4(0.f, 0.f, 0.f, 0.f);
    int j = beg;
    for (; j + 4 <= end; j += 4) {
        int s0 = __ldg(&g_col[j + 0]);
        int s1 = __ldg(&g_col[j + 1]);
        int s2 = __ldg(&g_col[j + 2]);
        int s3 = __ldg(&g_col[j + 3]);
        float4 v0 = __ldg(reinterpret_cast<const float4*>(feat + (size_t)s0 * IN_DIM) + lane);
        float4 v1 = __ldg(reinterpret_cast<const float4*>(feat + (size_t)s1 * IN_DIM) + lane);
        float4 v2 = __ldg(reinterpret_cast<const float4*>(feat + (size_t)s2 * IN_DIM) + lane);
        float4 v3 = __ldg(reinterpret_cast<const float4*>(feat + (size_t)s3 * IN_DIM) + lane);
        f4add(acc, v0); f4add(acc, v1); f4add(acc, v2); f4add(acc, v3);
    }
    for (; j < end; j++) {
        int s = __ldg(&g_col[j]);
        float4 v = __ldg(reinterpret_cast<const float4*>(feat + (size_t)s * IN_DIM) + lane);
        f4add(acc, v);
    }
    float inv = 1.0f / (float)max(end - beg, 1);
    float4 o;
    o.x = to_tf32(acc.x * inv); o.y = to_tf32(acc.y * inv);
    o.z = to_tf32(acc.z * inv); o.w = to_tf32(acc.w * inv);
    reinterpret_cast<float4*>(g_agg + (size_t)w * IN_DIM)[lane] = o;
}

__global__ void gather_mean_256() {
    int gw = (blockIdx.x * blockDim.x + threadIdx.x) >> 5;
    int node = gw >> 1;
    int half = gw & 1;
    int lane = threadIdx.x & 31;
    if (node >= N_NODES) return;
    int beg = g_rowptr[node], end = g_rowptr[node + 1];
    int fo = half * 32 + lane;
    const float4* h1v = reinterpret_cast<const float4*>(g_h1);
    float4 acc = make_float4(0.f, 0.f, 0.f, 0.f);
    int j = beg;
    for (; j + 4 <= end; j += 4) {
        int s0 = __ldg(&g_col[j + 0]);
        int s1 = __ldg(&g_col[j + 1]);
        int s2 = __ldg(&g_col[j + 2]);
        int s3 = __ldg(&g_col[j + 3]);
        float4 v0 = __ldg(h1v + (size_t)s0 * (HID / 4) + fo);
        float4 v1 = __ldg(h1v + (size_t)s1 * (HID / 4) + fo);
        float4 v2 = __ldg(h1v + (size_t)s2 * (HID / 4) + fo);
        float4 v3 = __ldg(h1v + (size_t)s3 * (HID / 4) + fo);
        f4add(acc, v0); f4add(acc, v1); f4add(acc, v2); f4add(acc, v3);
    }
    for (; j < end; j++) {
        int s = __ldg(&g_col[j]);
        f4add(acc, __ldg(h1v + (size_t)s * (HID / 4) + fo));
    }
    float inv = 1.0f / (float)max(end - beg, 1);
    float4 o;
    o.x = to_tf32(acc.x * inv); o.y = to_tf32(acc.y * inv);
    o.z = to_tf32(acc.z * inv); o.w = to_tf32(acc.w * inv);
    reinterpret_cast<float4*>(g_agg)[(size_t)node * (HID / 4) + fo] = o;
}

// ---------------- tf32 mma.sync SAGE GEMM, BM=128 BN=256 BK=32, 256 thr ----------------
// C[M,256] = relu( Avirt[M, 2*KHALF] @ W[2*KHALF, 256] + bias )
// Pair-packed smem: A as (k, k+4) float2 pairs, stride 40 floats/row;
// B as (W[k][n], W[k+4][n]) float2, row (k8*4+j) stride 520 floats.
// Register-staged double buffer (LDG->regs overlaps MMA; STS after).
#define A_STRIDE 40
#define B_STRIDE 520
#define A_FBUF (128 * A_STRIDE)     // 5120 floats
#define B_FBUF (16 * B_STRIDE)      // 8320 floats
#define GEMM_SMEM ((2 * A_FBUF + 2 * B_FBUF) * 4)   // 107520 B

template <int KHALF, bool CVT_OUT>
__global__ void __launch_bounds__(256, 1)
sage_mma(const float* __restrict__ A0, const float* __restrict__ A1,
         const float* __restrict__ W, const float* __restrict__ bias,
         float* __restrict__ C) {
    extern __shared__ float smf[];
    float* Abuf[2] = { smf, smf + A_FBUF };
    float* Bbuf[2] = { smf + 2 * A_FBUF, smf + 2 * A_FBUF + B_FBUF };

    const int tid = threadIdx.x;
    const int lane = tid & 31;
    const int wid = tid >> 5;
    const int wm = wid & 1;          // 2 m-groups x 64 rows
    const int wn = wid >> 1;         // 4 n-groups x 64 cols
    const int rowBase = blockIdx.x * 128;
    const int NT = (2 * KHALF) / 32;

    float acc[4][8][4];
#pragma unroll
    for (int i = 0; i < 4; i++)
#pragma unroll
        for (int j = 0; j < 8; j++)
#pragma unroll
            for (int k = 0; k < 4; k++) acc[i][j][k] = 0.0f;

    float4 av[2][2];   // A staging: [pass][h]
    float4 bv[4][2];   // B staging: [pass][row k / k+4]

    auto ldgA = [&](int kt) {
        const float* Ab = (kt * 32 < KHALF) ? A0 : A1;
        int kb = (kt * 32 < KHALF) ? kt * 32 : kt * 32 - KHALF;
#pragma unroll
        for (int p = 0; p < 2; p++) {
            int row = rowBase + p * 64 + (tid >> 2);
            if (row < N_NODES) {
                const float* s = Ab + (size_t)row * KHALF + kb + (tid & 3) * 8;
                av[p][0] = __ldg(reinterpret_cast<const float4*>(s));
                av[p][1] = __ldg(reinterpret_cast<const float4*>(s + 4));
            } else {
                av[p][0] = make_float4(0.f, 0.f, 0.f, 0.f);
                av[p][1] = make_float4(0.f, 0.f, 0.f, 0.f);
            }
        }
    };
    auto ldgB = [&](int kt) {
#pragma unroll
        for (int p = 0; p < 4; p++) {
            int kj = p * 4 + (tid >> 6);                 // 0..15
            int krow = kt * 32 + (kj >> 2) * 8 + (kj & 3);
            const float* s = W + (size_t)krow * HID + (tid & 63) * 4;
            bv[p][0] = __ldg(reinterpret_cast<const float4*>(s));
            bv[p][1] = __ldg(reinterpret_cast<const float4*>(s + 4 * HID));
        }
    };
    auto stsAB = [&](int buf) {
        float* A_ = Abuf[buf];
        float* B_ = Bbuf[buf];
#pragma unroll
        for (int p = 0; p < 2; p++) {
            int off = (p * 64 + (tid >> 2)) * A_STRIDE + (tid & 3) * 8;
            const float* x = reinterpret_cast<const float*>(&av[p][0]);
            const float* y = reinterpret_cast<const float*>(&av[p][1]);
#pragma unroll
            for (int j = 0; j < 4; j++)
                *reinterpret_cast<float2*>(A_ + off + j * 2) = make_float2(x[j], y[j]);
        }
#pragma unroll
        for (int p = 0; p < 4; p++) {
            int row = p * 4 + (tid >> 6);
            float* d = B_ + row * B_STRIDE + (tid & 63) * 8;
            float4 x = bv[p][0], y = bv[p][1];
            *reinterpret_cast<float4*>(d)     = make_float4(x.x, y.x, x.y, y.y);
            *reinterpret_cast<float4*>(d + 4) = make_float4(x.z, y.z, x.w, y.w);
        }
    };
    auto mmaTile = [&](int buf) {
        const float* A_ = Abuf[buf];
        const float* B_ = Bbuf[buf];
#pragma unroll
        for (int k8 = 0; k8 < 4; k8++) {
            uint32_t a[4][4];
#pragma unroll
            for (int mt = 0; mt < 4; mt++) {
                int m = wm * 64 + mt * 16 + (lane >> 2);
                float2 p0 = *reinterpret_cast<const float2*>(
                    A_ + m * A_STRIDE + k8 * 8 + (lane & 3) * 2);
                float2 p1 = *reinterpret_cast<const float2*>(
                    A_ + (m + 8) * A_STRIDE + k8 * 8 + (lane & 3) * 2);
                a[mt][0] = __float_as_uint(p0.x);
                a[mt][1] = __float_as_uint(p1.x);
                a[mt][2] = __float_as_uint(p0.y);
                a[mt][3] = __float_as_uint(p1.y);
            }
#pragma unroll
            for (int nt = 0; nt < 8; nt++) {
                int n = wn * 64 + nt * 8 + (lane >> 2);
                float2 bp = *reinterpret_cast<const float2*>(
                    B_ + (k8 * 4 + (lane & 3)) * B_STRIDE + 2 * n);
                uint32_t b0 = __float_as_uint(bp.x);
                uint32_t b1 = __float_as_uint(bp.y);
#pragma unroll
                for (int mt = 0; mt < 4; mt++)
                    mma_tf32(acc[mt][nt], a[mt], b0, b1);
            }
        }
    };

    ldgA(0); ldgB(0); stsAB(0);
    __syncthreads();
#pragma unroll 1
    for (int kt = 0; kt < NT; kt++) {
        if (kt + 1 < NT) { ldgA(kt + 1); ldgB(kt + 1); }
        mmaTile(kt & 1);
        if (kt + 1 < NT) stsAB((kt + 1) & 1);
        __syncthreads();
    }

    // epilogue: bias + relu (+tf32 round), direct float2 stores
#pragma unroll
    for (int mt = 0; mt < 4; mt++) {
        int r0 = rowBase + wm * 64 + mt * 16 + (lane >> 2);
#pragma unroll
        for (int nt = 0; nt < 8; nt++) {
            int c = wn * 64 + nt * 8 + (lane & 3) * 2;
            float bv0 = __ldg(bias + c);
            float bv1 = __ldg(bias + c + 1);
            float v0 = fmaxf(acc[mt][nt][0] + bv0, 0.0f);
            float v1 = fmaxf(acc[mt][nt][1] + bv1, 0.0f);
            float v2 = fmaxf(acc[mt][nt][2] + bv0, 0.0f);
            float v3 = fmaxf(acc[mt][nt][3] + bv1, 0.0f);
            if (CVT_OUT) {
                v0 = to_tf32(v0); v1 = to_tf32(v1);
                v2 = to_tf32(v2); v3 = to_tf32(v3);
            }
            if (r0 < N_NODES)
                *reinterpret_cast<float2*>(C + (size_t)r0 * HID + c) = make_float2(v0, v1);
            if (r0 + 8 < N_NODES)
                *reinterpret_cast<float2*>(C + (size_t)(r0 + 8) * HID + c) = make_float2(v2, v3);
        }
    }
}

// ---------------- classifier ----------------
__global__ void classifier_k(const float* __restrict__ wc,
                             const float* __restrict__ bc,
                             float* __restrict__ out) {
    __shared__ float w[HID * N_CLASSES];
    __shared__ float hrow[8][HID];
    for (int i = threadIdx.x; i < HID * N_CLASSES; i += blockDim.x)
        w[i] = wc[i];
    __syncthreads();

    int warp = threadIdx.x >> 5;
    int lane = threadIdx.x & 31;
    int row = blockIdx.x * 8 + warp;
    if (row >= N_NODES) return;

    const float* h = g_h2 + (size_t)row * HID;
    for (int k = lane; k < HID; k += 32) hrow[warp][k] = h[k];
    __syncwarp();

    int c = lane & 15;
    int p = lane >> 4;
    float acc = 0.0f;
    int kbeg = p * (HID / 2);
#pragma unroll 8
    for (int k = kbeg; k < kbeg + HID / 2; k++)
        acc += hrow[warp][k] * w[k * N_CLASSES + c];
    acc += __shfl_xor_sync(0xffffffffu, acc, 16);
    if (lane < 16) out[(size_t)row * N_CLASSES + lane] = acc + bc[lane];
}

// ---------------- launch ----------------
extern "C" void kernel_launch(void* const* d_in, const int* in_sizes, int n_in,
                              void* d_out, int out_size) {
    const float* x    = (const float*)d_in[0];
    const int*   ei   = (const int*)d_in[1];
    const float* w1_l = (const float*)d_in[2];
    const float* b1_l = (const float*)d_in[3];
    const float* w1_r = (const float*)d_in[4];
    const float* w2_l = (const float*)d_in[5];
    const float* b2_l = (const float*)d_in[6];
    const float* w2_r = (const float*)d_in[7];
    const float* wc   = (const float*)d_in[8];
    const float* bc   = (const float*)d_in[9];
    float* out = (float*)d_out;

    // resolve REAL device addresses (GB300 ATS pitfall: never pass symbols as args)
    void *p_agg, *p_h1, *p_h2, *p_w1t, *p_w2t;
    cudaGetSymbolAddress(&p_agg, g_agg);
    cudaGetSymbolAddress(&p_h1,  g_h1);
    cudaGetSymbolAddress(&p_h2,  g_h2);
    cudaGetSymbolAddress(&p_w1t, g_w1t);
    cudaGetSymbolAddress(&p_w2t, g_w2t);

    cudaFuncSetAttribute(sage_mma<IN_DIM, true>,
                         cudaFuncAttributeMaxDynamicSharedMemorySize, GEMM_SMEM);
    cudaFuncSetAttribute(sage_mma<HID, false>,
                         cudaFuncAttributeMaxDynamicSharedMemorySize, GEMM_SMEM);

    // ---- prep + CSR ----
    prep_k<<<(2 * HID * HID + 255) / 256, 256>>>(w1_l, w1_r, w2_l, w2_r);
    hist_kernel<<<(N_EDGES + 255) / 256, 256>>>(ei);
    block_reduce_k<<<N_SBLOCKS, SCAN_BLOCK>>>();
    scan_blocksums_k<<<1, 256>>>();
    block_scan_k<<<N_SBLOCKS, SCAN_BLOCK>>>();
    fill_kernel<<<(N_EDGES + 255) / 256, 256>>>(ei);

    // ---- layer 1 ----
    gather_mean_128<<<(N_NODES * 32 + 255) / 256, 256>>>(x);
    sage_mma<IN_DIM, true><<<(N_NODES + 127) / 128, 256, GEMM_SMEM>>>(
        (const float*)p_agg, x, (const float*)p_w1t, b1_l, (float*)p_h1);

    // ---- layer 2 ----
    gather_mean_256<<<(N_NODES * 2 * 32 + 255) / 256, 256>>>();
    sage_mma<HID, false><<<(N_NODES + 127) / 128, 256, GEMM_SMEM>>>(
        (const float*)p_agg, (const float*)p_h1, (const float*)p_w2t, b2_l, (float*)p_h2);

    // ---- classifier ----
    classifier_k<<<(N_NODES + 7) / 8, 256>>>(wc, bc, out);
}